// round 1
// baseline (speedup 1.0000x reference)
#include <cuda_runtime.h>
#include <math.h>

// Problem constants
#define TB   8        // batch
#define TD   512      // D
#define TDD  1024     // 2D
#define TT   4096     // T
#define NCTA 128
#define CJ   8        // h columns per CTA   (TDD / NCTA)
#define CI   4        // p columns per CTA   (TD  / NCTA)
#define NTHR 256
#define NWARP 8

// Persistent scratch (allocation-free rule: __device__ globals)
__device__ float    gMem[TB * TD];   // recurrent state
__device__ float    gH[TB * TDD];    // per-step hidden activations
__device__ unsigned g_bar;           // grid barrier counter

__global__ void init_scratch() {
    int t = blockIdx.x * blockDim.x + threadIdx.x;
    if (t < TB * TD) gMem[t] = 0.0f;
    if (t == 0) g_bar = 0u;
}

// packed fp32x2 FMA (Blackwell): 2 MACs per instruction
__device__ __forceinline__ void fma2(unsigned long long& acc,
                                     unsigned long long a,
                                     unsigned long long b) {
    asm volatile("fma.rn.f32x2 %0, %1, %2, %0;" : "+l"(acc) : "l"(a), "l"(b));
}
__device__ __forceinline__ float2 u2f(unsigned long long v) {
    float2 f;
    asm("mov.b64 {%0,%1}, %2;" : "=f"(f.x), "=f"(f.y) : "l"(v));
    return f;
}
// L2-only (L1-bypassing) 16B load — for cross-CTA-produced data
__device__ __forceinline__ ulonglong2 ldg128_cg(const void* p) {
    ulonglong2 v;
    asm volatile("ld.global.cg.v2.u64 {%0,%1}, [%2];"
                 : "=l"(v.x), "=l"(v.y) : "l"(p));
    return v;
}
// read-only cached 16B load — for the immutable x input
__device__ __forceinline__ ulonglong2 ldg128_nc(const void* p) {
    ulonglong2 v;
    asm volatile("ld.global.nc.v2.u64 {%0,%1}, [%2];"
                 : "=l"(v.x), "=l"(v.y) : "l"(p));
    return v;
}

// Grid-wide barrier: arrive (release-ish via fence+relaxed red) then spin.
// __threadfence() (membar.gl) on both sides: publishes this CTA's stores and
// invalidates stale L1 lines before post-barrier reads.
__device__ __forceinline__ void grid_bar(unsigned target) {
    __syncthreads();
    if (threadIdx.x == 0) {
        __threadfence();
        unsigned one = 1u;
        asm volatile("red.relaxed.gpu.add.u32 [%0], %1;"
                     :: "l"(&g_bar), "r"(one) : "memory");
        unsigned v;
        do {
            asm volatile("ld.relaxed.gpu.u32 %0, [%1];"
                         : "=r"(v) : "l"(&g_bar) : "memory");
        } while (v < target);
        __threadfence();
    }
    __syncthreads();
}

__global__ void __launch_bounds__(NTHR, 1)
sys2_kernel(const float* __restrict__ x,
            const float* __restrict__ W1,
            const float* __restrict__ b1,
            const float* __restrict__ W2,
            const float* __restrict__ b2,
            float* __restrict__ y)
{
    extern __shared__ float smem[];
    float* sW1   = smem;                     // CJ*TDD floats (32 KB)
    float* sW2   = sW1 + CJ * TDD;           // CI*TDD floats (16 KB)
    float* sPart = sW2 + CI * TDD;           // NWARP*TB*CJ = 512 floats
    float* sB1   = sPart + NWARP * TB * CJ;  // CJ
    float* sB2   = sB1 + CJ;                 // CI

    const int cta  = blockIdx.x;
    const int tid  = threadIdx.x;
    const int w    = tid >> 5;
    const int lane = tid & 31;
    const int b    = lane >> 2;   // batch owned by this lane
    const int kq   = lane & 3;    // k-phase within 16-wide chunk
    const int jbase = cta * CJ;
    const int ibase = cta * CI;

    // ---- stage this CTA's weight slices into SMEM (once) ----
    {
        const float4* g1 = (const float4*)(W1 + (size_t)jbase * TDD);
        float4* s1 = (float4*)sW1;
        for (int idx = tid; idx < CJ * TDD / 4; idx += NTHR) s1[idx] = g1[idx];
        const float4* g2 = (const float4*)(W2 + (size_t)ibase * TDD);
        float4* s2 = (float4*)sW2;
        for (int idx = tid; idx < CI * TDD / 4; idx += NTHR) s2[idx] = g2[idx];
        if (tid < CJ) sB1[tid] = b1[jbase + tid];
        if (tid < CI) sB2[tid] = b2[ibase + tid];
    }
    __syncthreads();

    unsigned gen = 0;

    for (int t = 0; t < TT; ++t) {
        // ================= GEMM1: h = gelu(W1 @ [x_t ; mem] + b1) ==========
        // warp w covers x-k in [w*64, w*64+64) and mem-k in the same range.
        unsigned long long acc[CJ];
#pragma unroll
        for (int j = 0; j < CJ; ++j) acc[j] = 0ull;

        const float* xrow = x + ((size_t)b * TT + t) * TD;
        const float* mrow = gMem + b * TD;

        ulonglong2 ex[4], em[4];
#pragma unroll
        for (int it = 0; it < 4; ++it) {
            const int k = (w << 6) + (it << 4) + (kq << 2);
            ex[it] = ldg128_nc(xrow + k);
            em[it] = ldg128_cg(mrow + k);
        }
#pragma unroll
        for (int it = 0; it < 4; ++it) {
            const int k = (w << 6) + (it << 4) + (kq << 2);
#pragma unroll
            for (int j = 0; j < CJ; ++j) {
                const ulonglong2 wv = *(const ulonglong2*)(sW1 + j * TDD + k);
                fma2(acc[j], wv.x, ex[it].x);
                fma2(acc[j], wv.y, ex[it].y);
            }
        }
#pragma unroll
        for (int it = 0; it < 4; ++it) {
            const int k = (w << 6) + (it << 4) + (kq << 2);
#pragma unroll
            for (int j = 0; j < CJ; ++j) {
                const ulonglong2 wv = *(const ulonglong2*)(sW1 + j * TDD + TD + k);
                fma2(acc[j], wv.x, em[it].x);
                fma2(acc[j], wv.y, em[it].y);
            }
        }
        // reduce over the 4 k-phase lanes (lane bits 0..1), then across warps
#pragma unroll
        for (int j = 0; j < CJ; ++j) {
            float2 f = u2f(acc[j]);
            float s = f.x + f.y;
            s += __shfl_xor_sync(0xffffffffu, s, 1);
            s += __shfl_xor_sync(0xffffffffu, s, 2);
            if (kq == 0) sPart[(w << 6) + (b << 3) + j] = s;
        }
        __syncthreads();
        if (tid < TB * CJ) {
            const int bb = tid >> 3, jj = tid & 7;
            float s = sB1[jj];
#pragma unroll
            for (int ww = 0; ww < NWARP; ++ww) s += sPart[(ww << 6) + (bb << 3) + jj];
            const float hval = 0.5f * s * (1.0f + erff(s * 0.70710678118654752f));
            gH[bb * TDD + jbase + jj] = hval;   // publish h slice
        }
        grid_bar(++gen * (unsigned)NCTA);       // h visible chip-wide

        // ================= GEMM2: p = W2 @ h + b2 ; gated mem update =======
        unsigned long long pacc[CI];
#pragma unroll
        for (int i = 0; i < CI; ++i) pacc[i] = 0ull;

        const float* hrow = gH + b * TDD;
        ulonglong2 eh[8];
#pragma unroll
        for (int it = 0; it < 8; ++it) {
            const int k = (w << 7) + (it << 4) + (kq << 2);
            eh[it] = ldg128_cg(hrow + k);
        }
#pragma unroll
        for (int it = 0; it < 8; ++it) {
            const int k = (w << 7) + (it << 4) + (kq << 2);
#pragma unroll
            for (int i = 0; i < CI; ++i) {
                const ulonglong2 wv = *(const ulonglong2*)(sW2 + i * TDD + k);
                fma2(pacc[i], wv.x, eh[it].x);
                fma2(pacc[i], wv.y, eh[it].y);
            }
        }
#pragma unroll
        for (int i = 0; i < CI; ++i) {
            float2 f = u2f(pacc[i]);
            float s = f.x + f.y;
            s += __shfl_xor_sync(0xffffffffu, s, 1);
            s += __shfl_xor_sync(0xffffffffu, s, 2);
            if (kq == 0) sPart[(w << 5) + (b << 2) + i] = s;
        }
        __syncthreads();
        if (tid < TB * CI) {
            const int bb = tid >> 2, ii = tid & 3;
            float p = sB2[ii];
#pragma unroll
            for (int ww = 0; ww < NWARP; ++ww) p += sPart[(ww << 5) + (bb << 2) + ii];
            const float g = 1.0f / (1.0f + expf(-p));
            float m = gMem[bb * TD + ibase + ii];
            m = fmaf(p - m, g, m);                   // m*(1-g) + p*g
            gMem[bb * TD + ibase + ii] = m;
            y[((size_t)bb * TT + t) * TD + ibase + ii] = m;
        }
        grid_bar(++gen * (unsigned)NCTA);       // mem visible chip-wide
    }
}

extern "C" void kernel_launch(void* const* d_in, const int* in_sizes, int n_in,
                              void* d_out, int out_size) {
    const float* x  = (const float*)d_in[0];
    const float* W1 = (const float*)d_in[1];
    const float* b1 = (const float*)d_in[2];
    const float* W2 = (const float*)d_in[3];
    const float* b2 = (const float*)d_in[4];
    float* y = (float*)d_out;

    const size_t SMEM_BYTES =
        (CJ * TDD + CI * TDD + NWARP * TB * CJ + CJ + CI) * sizeof(float);
    cudaFuncSetAttribute(sys2_kernel,
                         cudaFuncAttributeMaxDynamicSharedMemorySize,
                         (int)SMEM_BYTES);

    init_scratch<<<(TB * TD + 255) / 256, 256>>>();
    sys2_kernel<<<NCTA, NTHR, SMEM_BYTES>>>(x, W1, b1, W2, b2, y);
}